// round 7
// baseline (speedup 1.0000x reference)
#include <cuda_runtime.h>
#include <cuda_bf16.h>
#include <math.h>
#include <stdint.h>

#define BB 4096
#define DD 128
#define NN 8192
#define NBLK 64                   // 128-row blocks
#define NTILES 2080               // NBLK*(NBLK+1)/2 upper-triangular tiles
#define GRID_SIM 296              // 2 CTAs per SM
#define EXS 2.885390082f          // 2 * log2(e)  (1/T = 2)

// ---------------- device scratch ----------------
__device__ __align__(16) float   g_Z[NN * DD];     // fp32 normalized (pos dots)
__device__ __align__(16) uint8_t g_Zf8[NN * DD];   // e4m3 normalized (GEMM)
__device__ float g_part[NBLK * NN];                // single writer per cell
__device__ float g_red[64];
__device__ unsigned g_fin;                         // monotonic last-block counter

// ---------------- helpers ----------------
__device__ __forceinline__ uint32_t smem_u32(const void* p) {
    uint32_t a;
    asm("{ .reg .u64 t; cvta.to.shared.u64 t, %1; cvt.u32.u64 %0, t; }"
        : "=r"(a) : "l"(p));
    return a;
}
__device__ __forceinline__ float ex2(float x) {
    float y;
    asm("ex2.approx.ftz.f32 %0, %1;" : "=f"(y) : "f"(x));
    return y;
}
__device__ __forceinline__ void ldsm4(uint32_t (&r)[4], uint32_t addr) {
    asm volatile("ldmatrix.sync.aligned.m8n8.x4.shared.b16 {%0,%1,%2,%3}, [%4];"
                 : "=r"(r[0]), "=r"(r[1]), "=r"(r[2]), "=r"(r[3]) : "r"(addr));
}
// fp8 e4m3 MMA: m16n8k32, fp32 accumulate
__device__ __forceinline__ void mma_f8(float (&d)[4], const uint32_t (&a)[4],
                                       uint32_t b0, uint32_t b1) {
    asm volatile("mma.sync.aligned.m16n8k32.row.col.f32.e4m3.e4m3.f32 "
                 "{%0,%1,%2,%3},{%4,%5,%6,%7},{%8,%9},{%0,%1,%2,%3};"
                 : "+f"(d[0]), "+f"(d[1]), "+f"(d[2]), "+f"(d[3])
                 : "r"(a[0]), "r"(a[1]), "r"(a[2]), "r"(a[3]), "r"(b0), "r"(b1));
}
__device__ __forceinline__ void cp16(uint32_t s, const void* g) {
    asm volatile("cp.async.cg.shared.global [%0], [%1], 16;" :: "r"(s), "l"(g));
}
#define CP_COMMIT() asm volatile("cp.async.commit_group;" ::: "memory")
#define CP_WAIT0()  asm volatile("cp.async.wait_group 0;" ::: "memory")

// idx -> (rt, ct), ct >= rt, row-major over the upper triangle
__device__ __forceinline__ void tile_map(int idx, int& rt, int& ct) {
    float f = 129.0f * 129.0f - 8.0f * (float)idx;
    int r = (int)((129.0f - sqrtf(f)) * 0.5f);
    if (r > 63) r = 63;
    if (r < 0) r = 0;
    while (r * (129 - r) / 2 > idx) --r;
    while ((r + 1) * (128 - r) / 2 <= idx) ++r;
    rt = r;
    ct = r + (idx - r * (129 - r) / 2);
}

// cp.async a 128x128 e4m3 block (16 KB) into swizzled smem (256 threads)
__device__ __forceinline__ void cpa_tile(uint32_t sbase, int rowBase, int tid) {
    const char* g = (const char*)g_Zf8 + (size_t)rowBase * 128;
    #pragma unroll
    for (int i = 0; i < 4; i++) {
        int idx = tid + 256 * i;          // 1024 chunks of 16B
        int r = idx >> 3, c8 = idx & 7;
        cp16(sbase + (uint32_t)(r * 128 + ((c8 ^ (r & 7)) << 4)),
             g + r * 128 + c8 * 16);
    }
}

// ---------------------------------------------------------------------------
// 1) L2-normalize (one warp/row) -> fp32 + e4m3 copies
// ---------------------------------------------------------------------------
__global__ void k_normalize(const float* __restrict__ zi,
                            const float* __restrict__ zj) {
    int warp = (blockIdx.x * blockDim.x + threadIdx.x) >> 5;
    int lane = threadIdx.x & 31;
    if (warp >= NN) return;
    const float* src = (warp < BB) ? (zi + (size_t)warp * DD)
                                   : (zj + (size_t)(warp - BB) * DD);
    float4 v = ((const float4*)src)[lane];
    float s = v.x * v.x + v.y * v.y + v.z * v.z + v.w * v.w;
    #pragma unroll
    for (int o = 16; o; o >>= 1) s += __shfl_xor_sync(0xffffffffu, s, o);
    float inv = 1.0f / fmaxf(sqrtf(s), 1e-12f);
    float4 o4 = make_float4(v.x * inv, v.y * inv, v.z * inv, v.w * inv);
    ((float4*)(g_Z + (size_t)warp * DD))[lane] = o4;
    uint16_t lo, hi;
    asm("cvt.rn.satfinite.e4m3x2.f32 %0, %1, %2;" : "=h"(lo) : "f"(o4.y), "f"(o4.x));
    asm("cvt.rn.satfinite.e4m3x2.f32 %0, %1, %2;" : "=h"(hi) : "f"(o4.w), "f"(o4.z));
    ((uint32_t*)(g_Zf8 + (size_t)warp * DD))[lane] = (uint32_t)lo | ((uint32_t)hi << 16);
}

// ---------------------------------------------------------------------------
// 2) Triangular FP8 MMA Gram, contiguous chunks, A-resident, occupancy 2.
// ---------------------------------------------------------------------------
__global__ void __launch_bounds__(256, 2) k_sim() {
    extern __shared__ char dyn[];
    __shared__ float sRow[2][128];
    __shared__ float sCol[4][128];

    char* sm0 = (char*)(((uintptr_t)dyn + 1023) & ~(uintptr_t)1023);
    uint32_t su = smem_u32(sm0);
    uint32_t suA = su;                               // 16 KB
    uint32_t suB[2] = {su + 16384u, su + 32768u};    // 2 x 16 KB

    int tid = threadIdx.x;
    int wid = tid >> 5, lane = tid & 31;
    int warpM = (wid >> 1) * 32;
    int warpN = (wid & 1) * 64;

    // shared lane geometry for A and B fragments (e4m3 m16n8k32)
    int rowoff = (lane & 7) + 8 * ((lane >> 3) & 1);
    int cpart  = lane >> 4;                 // 0/1: k bytes 0-15 / 16-31
    int xm     = lane & 7;

    // contiguous chunk: 8 CTAs x 8 tiles, 288 CTAs x 7 tiles
    int c = blockIdx.x;
    int start = c * 7 + (c < 8 ? c : 8);
    int count = (c < 8) ? 8 : 7;
    int rt, ct;
    tile_map(start, rt, ct);

    cpa_tile(suA, rt * 128, tid);
    cpa_tile(suB[0], ct * 128, tid);
    CP_COMMIT();
    CP_WAIT0();
    __syncthreads();

    int bi = 0;
    for (int i = 0; i < count; i++) {
        int nrt = rt, nct = ct + 1;
        if (nct == NBLK) { nrt = rt + 1; nct = nrt; }
        bool have_next = (i + 1 < count);
        bool sameA = have_next && (nrt == rt);
        if (sameA) {
            cpa_tile(suB[bi ^ 1], nct * 128, tid);
            CP_COMMIT();
        }

        uint32_t bufB = suB[bi];
        uint32_t aAddr0 = suA + (uint32_t)(warpM + rowoff) * 128u;
        uint32_t aAddr1 = aAddr0 + 16u * 128u;

        float acc[2][8][4];
        #pragma unroll
        for (int mt = 0; mt < 2; mt++)
            #pragma unroll
            for (int nt = 0; nt < 8; nt++)
                #pragma unroll
                for (int e = 0; e < 4; e++) acc[mt][nt][e] = 0.f;

        #pragma unroll
        for (int kk = 0; kk < 4; kk++) {            // 4 k-steps of k32
            uint32_t cc = (uint32_t)(((2 * kk + cpart) ^ xm) << 4);
            uint32_t a0[4], a1[4];
            ldsm4(a0, aAddr0 + cc);
            ldsm4(a1, aAddr1 + cc);
            #pragma unroll
            for (int ng = 0; ng < 4; ng++) {
                uint32_t b[4];
                ldsm4(b, bufB + (uint32_t)(warpN + ng * 16 + rowoff) * 128u + cc);
                mma_f8(acc[0][2 * ng],     a0, b[0], b[2]);
                mma_f8(acc[0][2 * ng + 1], a0, b[1], b[3]);
                mma_f8(acc[1][2 * ng],     a1, b[0], b[2]);
                mma_f8(acc[1][2 * ng + 1], a1, b[1], b[3]);
            }
        }

        // ---- fused epilogue (acc layout unchanged) ----
        float rowp[2][2] = {{0.f, 0.f}, {0.f, 0.f}};
        if (rt != ct) {
            #pragma unroll
            for (int nt = 0; nt < 8; nt++) {
                float e0 = ex2(acc[0][nt][0] * EXS);
                float e1 = ex2(acc[0][nt][1] * EXS);
                float e2 = ex2(acc[0][nt][2] * EXS);
                float e3 = ex2(acc[0][nt][3] * EXS);
                float f0 = ex2(acc[1][nt][0] * EXS);
                float f1 = ex2(acc[1][nt][1] * EXS);
                float f2 = ex2(acc[1][nt][2] * EXS);
                float f3 = ex2(acc[1][nt][3] * EXS);
                rowp[0][0] += e0 + e1; rowp[0][1] += e2 + e3;
                rowp[1][0] += f0 + f1; rowp[1][1] += f2 + f3;
                float cq0 = e0 + e2 + f0 + f2;
                float cq1 = e1 + e3 + f1 + f3;
                cq0 += __shfl_xor_sync(0xffffffffu, cq0, 4);
                cq0 += __shfl_xor_sync(0xffffffffu, cq0, 8);
                cq0 += __shfl_xor_sync(0xffffffffu, cq0, 16);
                cq1 += __shfl_xor_sync(0xffffffffu, cq1, 4);
                cq1 += __shfl_xor_sync(0xffffffffu, cq1, 8);
                cq1 += __shfl_xor_sync(0xffffffffu, cq1, 16);
                if (lane < 4) {
                    sCol[wid >> 1][warpN + nt * 8 + lane * 2]     = cq0;
                    sCol[wid >> 1][warpN + nt * 8 + lane * 2 + 1] = cq1;
                }
            }
        } else {
            #pragma unroll
            for (int mt = 0; mt < 2; mt++) {
                int r0 = warpM + mt * 16 + (lane >> 2);
                #pragma unroll
                for (int nt = 0; nt < 8; nt++) {
                    int c0 = warpN + nt * 8 + (lane & 3) * 2;
                    float e0 = ex2(acc[mt][nt][0] * EXS);
                    float e1 = ex2(acc[mt][nt][1] * EXS);
                    float e2 = ex2(acc[mt][nt][2] * EXS);
                    float e3 = ex2(acc[mt][nt][3] * EXS);
                    rowp[mt][0] += (r0 == c0     ? 0.f : e0) + (r0 == c0 + 1     ? 0.f : e1);
                    rowp[mt][1] += (r0 + 8 == c0 ? 0.f : e2) + (r0 + 8 == c0 + 1 ? 0.f : e3);
                }
            }
        }
        #pragma unroll
        for (int mt = 0; mt < 2; mt++)
            #pragma unroll
            for (int h = 0; h < 2; h++) {
                float v = rowp[mt][h];
                v += __shfl_xor_sync(0xffffffffu, v, 1);
                v += __shfl_xor_sync(0xffffffffu, v, 2);
                if ((lane & 3) == 0)
                    sRow[wid & 1][warpM + mt * 16 + 8 * h + (lane >> 2)] = v;
            }
        __syncthreads();

        if (tid < 128) {
            float rv = sRow[0][tid] + sRow[1][tid];
            g_part[(size_t)ct * NN + rt * 128 + tid] = rv;
            if (rt != ct) {
                float cv = sCol[0][tid] + sCol[1][tid] + sCol[2][tid] + sCol[3][tid];
                g_part[(size_t)rt * NN + ct * 128 + tid] = cv;
            }
        }

        if (have_next) {
            if (sameA) {
                CP_WAIT0();
                __syncthreads();
            } else {
                __syncthreads();
                cpa_tile(suA, nrt * 128, tid);
                cpa_tile(suB[bi ^ 1], nct * 128, tid);
                CP_COMMIT();
                CP_WAIT0();
                __syncthreads();
            }
            bi ^= 1;
        }
        rt = nrt; ct = nct;
    }
}

// ---------------------------------------------------------------------------
// 3) Final reduction, single kernel (replay-safe last-block pattern)
// ---------------------------------------------------------------------------
__global__ void k_final(float* __restrict__ out) {
    __shared__ float sred[128];
    __shared__ unsigned s_last;
    int tid = threadIdx.x;
    int row = blockIdx.x * 128 + tid;
    float rs = 0.f;
    #pragma unroll
    for (int s = 0; s < NBLK; s++) rs += g_part[(size_t)s * NN + row];
    const float4* a = (const float4*)(g_Z + (size_t)row * DD);
    const float4* b = (const float4*)(g_Z + (size_t)(row ^ BB) * DD);
    float dot = 0.f;
    #pragma unroll
    for (int j = 0; j < 32; j++) {
        float4 va = a[j], vb = b[j];
        dot += va.x * vb.x + va.y * vb.y + va.z * vb.z + va.w * vb.w;
    }
    sred[tid] = logf(rs) - 2.0f * dot;
    __syncthreads();
    #pragma unroll
    for (int o = 64; o; o >>= 1) {
        if (tid < o) sred[tid] += sred[tid + o];
        __syncthreads();
    }
    if (tid == 0) {
        g_red[blockIdx.x] = sred[0];
        __threadfence();
        unsigned old = atomicAdd(&g_fin, 1u);   // monotonic: replay-safe
        s_last = (old % 64u == 63u) ? 1u : 0u;
    }
    __syncthreads();
    if (s_last) {
        __threadfence();
        float v = (tid < 64) ? *((volatile float*)&g_red[tid]) : 0.f;
        sred[tid] = v;
        __syncthreads();
        #pragma unroll
        for (int o = 64; o; o >>= 1) {
            if (tid < o) sred[tid] += sred[tid + o];
            __syncthreads();
        }
        if (tid == 0) out[0] = sred[0] / (float)NN;
    }
}

// ---------------------------------------------------------------------------
extern "C" void kernel_launch(void* const* d_in, const int* in_sizes, int n_in,
                              void* d_out, int out_size) {
    (void)in_sizes; (void)n_in; (void)out_size;
    const float* zi = (const float*)d_in[0];
    const float* zj = (const float*)d_in[1];
    float* out = (float*)d_out;

    size_t smem = 1024 + 3 * 16384;   // pad + A + 2x B = 50 KB -> 2 CTAs/SM
    cudaFuncSetAttribute(k_sim, cudaFuncAttributeMaxDynamicSharedMemorySize,
                         (int)smem);

    k_normalize<<<NN / 8, 256>>>(zi, zj);
    k_sim<<<GRID_SIM, 256, smem>>>();
    k_final<<<64, 128>>>(out);
}

// round 8
// speedup vs baseline: 1.2080x; 1.2080x over previous
#include <cuda_runtime.h>
#include <cuda_bf16.h>
#include <math.h>
#include <stdint.h>

#define BB 4096
#define DD 128
#define NN 8192
#define NBLK 64                   // 128-row blocks
#define NTILES 2080               // NBLK*(NBLK+1)/2 upper-triangular tiles
#define GRID_SIM 296              // 2 CTAs per SM
#define EXS 2.885390082f          // 2 * log2(e)  (1/T = 2)

// ---------------- device scratch ----------------
__device__ __align__(16) __nv_bfloat16 g_Zh[NN * DD];  // bf16 normalized rows
__device__ float g_part[NBLK * NN];   // slot s, row r: unique single writer
__device__ float g_red[256];
__device__ unsigned g_fin;            // monotonic last-block counter

// ---------------- helpers ----------------
__device__ __forceinline__ uint32_t smem_u32(const void* p) {
    uint32_t a;
    asm("{ .reg .u64 t; cvta.to.shared.u64 t, %1; cvt.u32.u64 %0, t; }"
        : "=r"(a) : "l"(p));
    return a;
}
__device__ __forceinline__ float ex2(float x) {
    float y;
    asm("ex2.approx.ftz.f32 %0, %1;" : "=f"(y) : "f"(x));
    return y;
}
__device__ __forceinline__ void ldsm4(uint32_t (&r)[4], uint32_t addr) {
    asm volatile("ldmatrix.sync.aligned.m8n8.x4.shared.b16 {%0,%1,%2,%3}, [%4];"
                 : "=r"(r[0]), "=r"(r[1]), "=r"(r[2]), "=r"(r[3]) : "r"(addr));
}
__device__ __forceinline__ void mma16816(float (&d)[4], const uint32_t (&a)[4],
                                         uint32_t b0, uint32_t b1) {
    asm volatile("mma.sync.aligned.m16n8k16.row.col.f32.bf16.bf16.f32 "
                 "{%0,%1,%2,%3},{%4,%5,%6,%7},{%8,%9},{%0,%1,%2,%3};"
                 : "+f"(d[0]), "+f"(d[1]), "+f"(d[2]), "+f"(d[3])
                 : "r"(a[0]), "r"(a[1]), "r"(a[2]), "r"(a[3]), "r"(b0), "r"(b1));
}
__device__ __forceinline__ void cp16(uint32_t s, const void* g) {
    asm volatile("cp.async.cg.shared.global [%0], [%1], 16;" :: "r"(s), "l"(g));
}
#define CP_COMMIT() asm volatile("cp.async.commit_group;" ::: "memory")
#define CP_WAIT0()  asm volatile("cp.async.wait_group 0;" ::: "memory")

// idx -> (rt, ct), ct >= rt, row-major over the upper triangle
__device__ __forceinline__ void tile_map(int idx, int& rt, int& ct) {
    float f = 129.0f * 129.0f - 8.0f * (float)idx;
    int r = (int)((129.0f - sqrtf(f)) * 0.5f);
    if (r > 63) r = 63;
    if (r < 0) r = 0;
    while (r * (129 - r) / 2 > idx) --r;
    while ((r + 1) * (128 - r) / 2 <= idx) ++r;
    rt = r;
    ct = r + (idx - r * (129 - r) / 2);
}

// cp.async a 128x128 bf16 block into a swizzled smem tile (all 256 threads)
__device__ __forceinline__ void cpa_tile(uint32_t sbase, int rowBase, int tid) {
    const char* g = (const char*)g_Zh + (size_t)rowBase * 256;
    #pragma unroll
    for (int i = 0; i < 8; i++) {
        int idx = tid + 256 * i;
        int r = idx >> 4, c4 = idx & 15;
        cp16(sbase + (uint32_t)(r * 256 + ((c4 ^ (r & 7)) << 4)),
             g + r * 256 + c4 * 16);
    }
}

// ---------------------------------------------------------------------------
// 1) L2-normalize -> bf16 only; two rows per warp for ILP
// ---------------------------------------------------------------------------
__global__ void k_normalize(const float* __restrict__ zi,
                            const float* __restrict__ zj) {
    int warp = (blockIdx.x * blockDim.x + threadIdx.x) >> 5;   // 0..4095
    int lane = threadIdx.x & 31;
    int r0 = warp * 2, r1 = r0 + 1;
    const float* s0 = (r0 < BB) ? (zi + (size_t)r0 * DD)
                                : (zj + (size_t)(r0 - BB) * DD);
    const float* s1 = (r1 < BB) ? (zi + (size_t)r1 * DD)
                                : (zj + (size_t)(r1 - BB) * DD);
    float4 v0 = ((const float4*)s0)[lane];
    float4 v1 = ((const float4*)s1)[lane];
    float a = v0.x * v0.x + v0.y * v0.y + v0.z * v0.z + v0.w * v0.w;
    float b = v1.x * v1.x + v1.y * v1.y + v1.z * v1.z + v1.w * v1.w;
    #pragma unroll
    for (int o = 16; o; o >>= 1) {
        a += __shfl_xor_sync(0xffffffffu, a, o);
        b += __shfl_xor_sync(0xffffffffu, b, o);
    }
    float ia = 1.0f / fmaxf(sqrtf(a), 1e-12f);
    float ib = 1.0f / fmaxf(sqrtf(b), 1e-12f);
    __nv_bfloat162* d0 = (__nv_bfloat162*)(g_Zh + (size_t)r0 * DD);
    __nv_bfloat162* d1 = (__nv_bfloat162*)(g_Zh + (size_t)r1 * DD);
    d0[lane * 2]     = __floats2bfloat162_rn(v0.x * ia, v0.y * ia);
    d0[lane * 2 + 1] = __floats2bfloat162_rn(v0.z * ia, v0.w * ia);
    d1[lane * 2]     = __floats2bfloat162_rn(v1.x * ib, v1.y * ib);
    d1[lane * 2 + 1] = __floats2bfloat162_rn(v1.z * ib, v1.w * ib);
}

// ---------------------------------------------------------------------------
// 2) Triangular HMMA Gram, contiguous chunks, A-resident, occupancy 2.
//    (R6 core, unchanged — proven 43.6 us configuration)
// ---------------------------------------------------------------------------
__global__ void __launch_bounds__(256, 2) k_sim() {
    extern __shared__ char dyn[];
    __shared__ float sRow[2][128];
    __shared__ float sCol[4][128];

    char* sm0 = (char*)(((uintptr_t)dyn + 1023) & ~(uintptr_t)1023);
    uint32_t su = smem_u32(sm0);
    uint32_t suA = su;                 // 32 KB
    uint32_t suB[2] = {su + 32768u, su + 65536u};

    int tid = threadIdx.x;
    int wid = tid >> 5, lane = tid & 31;
    int warpM = (wid >> 1) * 32;
    int warpN = (wid & 1) * 64;

    int subA = lane >> 3;
    int rowoffA = (lane & 7) + 8 * (subA & 1);
    int cpartA = subA >> 1;
    int noffB = (lane & 7) + 8 * (subA >> 1);
    int cpartB = subA & 1;
    int xm = lane & 7;

    int c = blockIdx.x;
    int start = c * 7 + (c < 8 ? c : 8);
    int count = (c < 8) ? 8 : 7;
    int rt, ct;
    tile_map(start, rt, ct);

    cpa_tile(suA, rt * 128, tid);
    cpa_tile(suB[0], ct * 128, tid);
    CP_COMMIT();
    CP_WAIT0();
    __syncthreads();

    int bi = 0;
    for (int i = 0; i < count; i++) {
        int nrt = rt, nct = ct + 1;
        if (nct == NBLK) { nrt = rt + 1; nct = nrt; }
        bool have_next = (i + 1 < count);
        bool sameA = have_next && (nrt == rt);
        if (sameA) {
            cpa_tile(suB[bi ^ 1], nct * 128, tid);
            CP_COMMIT();
        }

        uint32_t bufB = suB[bi];
        uint32_t aAddr0 = suA + (uint32_t)(warpM + rowoffA) * 256u;
        uint32_t aAddr1 = aAddr0 + 16u * 256u;

        float acc[2][8][4];
        #pragma unroll
        for (int mt = 0; mt < 2; mt++)
            #pragma unroll
            for (int nt = 0; nt < 8; nt++)
                #pragma unroll
                for (int e = 0; e < 4; e++) acc[mt][nt][e] = 0.f;

        #pragma unroll
        for (int kk = 0; kk < 8; kk++) {
            uint32_t ca = (uint32_t)(((2 * kk + cpartA) ^ xm) << 4);
            uint32_t cb = (uint32_t)(((2 * kk + cpartB) ^ xm) << 4);
            uint32_t a0[4], a1[4];
            ldsm4(a0, aAddr0 + ca);
            ldsm4(a1, aAddr1 + ca);
            #pragma unroll
            for (int ng = 0; ng < 4; ng++) {
                uint32_t b[4];
                ldsm4(b, bufB + (uint32_t)(warpN + ng * 16 + noffB) * 256u + cb);
                mma16816(acc[0][2 * ng],     a0, b[0], b[1]);
                mma16816(acc[0][2 * ng + 1], a0, b[2], b[3]);
                mma16816(acc[1][2 * ng],     a1, b[0], b[1]);
                mma16816(acc[1][2 * ng + 1], a1, b[2], b[3]);
            }
        }

        // ---- fused epilogue ----
        float rowp[2][2] = {{0.f, 0.f}, {0.f, 0.f}};
        if (rt != ct) {
            #pragma unroll
            for (int nt = 0; nt < 8; nt++) {
                float e0 = ex2(acc[0][nt][0] * EXS);
                float e1 = ex2(acc[0][nt][1] * EXS);
                float e2 = ex2(acc[0][nt][2] * EXS);
                float e3 = ex2(acc[0][nt][3] * EXS);
                float f0 = ex2(acc[1][nt][0] * EXS);
                float f1 = ex2(acc[1][nt][1] * EXS);
                float f2 = ex2(acc[1][nt][2] * EXS);
                float f3 = ex2(acc[1][nt][3] * EXS);
                rowp[0][0] += e0 + e1; rowp[0][1] += e2 + e3;
                rowp[1][0] += f0 + f1; rowp[1][1] += f2 + f3;
                float cq0 = e0 + e2 + f0 + f2;
                float cq1 = e1 + e3 + f1 + f3;
                cq0 += __shfl_xor_sync(0xffffffffu, cq0, 4);
                cq0 += __shfl_xor_sync(0xffffffffu, cq0, 8);
                cq0 += __shfl_xor_sync(0xffffffffu, cq0, 16);
                cq1 += __shfl_xor_sync(0xffffffffu, cq1, 4);
                cq1 += __shfl_xor_sync(0xffffffffu, cq1, 8);
                cq1 += __shfl_xor_sync(0xffffffffu, cq1, 16);
                if (lane < 4) {
                    sCol[wid >> 1][warpN + nt * 8 + lane * 2]     = cq0;
                    sCol[wid >> 1][warpN + nt * 8 + lane * 2 + 1] = cq1;
                }
            }
        } else {
            #pragma unroll
            for (int mt = 0; mt < 2; mt++) {
                int r0 = warpM + mt * 16 + (lane >> 2);
                #pragma unroll
                for (int nt = 0; nt < 8; nt++) {
                    int c0 = warpN + nt * 8 + (lane & 3) * 2;
                    float e0 = ex2(acc[mt][nt][0] * EXS);
                    float e1 = ex2(acc[mt][nt][1] * EXS);
                    float e2 = ex2(acc[mt][nt][2] * EXS);
                    float e3 = ex2(acc[mt][nt][3] * EXS);
                    rowp[mt][0] += (r0 == c0     ? 0.f : e0) + (r0 == c0 + 1     ? 0.f : e1);
                    rowp[mt][1] += (r0 + 8 == c0 ? 0.f : e2) + (r0 + 8 == c0 + 1 ? 0.f : e3);
                }
            }
        }
        #pragma unroll
        for (int mt = 0; mt < 2; mt++)
            #pragma unroll
            for (int h = 0; h < 2; h++) {
                float v = rowp[mt][h];
                v += __shfl_xor_sync(0xffffffffu, v, 1);
                v += __shfl_xor_sync(0xffffffffu, v, 2);
                if ((lane & 3) == 0)
                    sRow[wid & 1][warpM + mt * 16 + 8 * h + (lane >> 2)] = v;
            }
        __syncthreads();

        if (tid < 128) {
            float rv = sRow[0][tid] + sRow[1][tid];
            g_part[(size_t)ct * NN + rt * 128 + tid] = rv;
            if (rt != ct) {
                float cv = sCol[0][tid] + sCol[1][tid] + sCol[2][tid] + sCol[3][tid];
                g_part[(size_t)rt * NN + ct * 128 + tid] = cv;
            }
        }

        if (have_next) {
            if (sameA) {
                CP_WAIT0();
                __syncthreads();
            } else {
                __syncthreads();
                cpa_tile(suA, nrt * 128, tid);
                cpa_tile(suB[bi ^ 1], nct * 128, tid);
                CP_COMMIT();
                CP_WAIT0();
                __syncthreads();
            }
            bi ^= 1;
        }
        rt = nrt; ct = nct;
    }
}

// ---------------------------------------------------------------------------
// 3) Final reduction: 8 lanes per row; positives from RAW inputs.
//    pos_logit = 2 * dot(zi,zj) / (||zi|| * ||zj||)  (== normalized dot / T)
// ---------------------------------------------------------------------------
__global__ void k_final(const float* __restrict__ zi,
                        const float* __restrict__ zj,
                        float* __restrict__ out) {
    __shared__ float sred[256];
    __shared__ unsigned s_last;
    int tid = threadIdx.x;
    int sub = tid & 7;                       // 8 lanes per row
    int row = blockIdx.x * 32 + (tid >> 3);

    // row-sum of exp: 8 slots per lane
    float rs = 0.f;
    #pragma unroll
    for (int k = 0; k < 8; k++)
        rs += g_part[(size_t)(sub + 8 * k) * NN + row];

    // positive-pair terms from raw inputs (16 elems per lane)
    int pr = row & (BB - 1);
    const float4* a = (const float4*)(zi + (size_t)pr * DD);
    const float4* b = (const float4*)(zj + (size_t)pr * DD);
    float dab = 0.f, naa = 0.f, nbb = 0.f;
    #pragma unroll
    for (int j = 0; j < 4; j++) {
        float4 va = a[sub * 4 + j], vb = b[sub * 4 + j];
        dab += va.x * vb.x + va.y * vb.y + va.z * vb.z + va.w * vb.w;
        naa += va.x * va.x + va.y * va.y + va.z * va.z + va.w * va.w;
        nbb += vb.x * vb.x + vb.y * vb.y + vb.z * vb.z + vb.w * vb.w;
    }
    #pragma unroll
    for (int o = 1; o < 8; o <<= 1) {
        rs  += __shfl_xor_sync(0xffffffffu, rs,  o);
        dab += __shfl_xor_sync(0xffffffffu, dab, o);
        naa += __shfl_xor_sync(0xffffffffu, naa, o);
        nbb += __shfl_xor_sync(0xffffffffu, nbb, o);
    }
    float v = 0.f;
    if (sub == 0) {
        float na = fmaxf(sqrtf(naa), 1e-12f);
        float nb = fmaxf(sqrtf(nbb), 1e-12f);
        v = logf(rs) - 2.0f * dab / (na * nb);
    }
    sred[tid] = v;
    __syncthreads();
    #pragma unroll
    for (int o = 128; o; o >>= 1) {
        if (tid < o) sred[tid] += sred[tid + o];
        __syncthreads();
    }
    if (tid == 0) {
        g_red[blockIdx.x] = sred[0];
        __threadfence();
        unsigned old = atomicAdd(&g_fin, 1u);   // monotonic: replay-safe
        s_last = (old % 256u == 255u) ? 1u : 0u;
    }
    __syncthreads();
    if (s_last) {
        __threadfence();
        sred[tid] = *((volatile float*)&g_red[tid]);
        __syncthreads();
        #pragma unroll
        for (int o = 128; o; o >>= 1) {
            if (tid < o) sred[tid] += sred[tid + o];
            __syncthreads();
        }
        if (tid == 0) out[0] = sred[0] / (float)NN;
    }
}

// ---------------------------------------------------------------------------
extern "C" void kernel_launch(void* const* d_in, const int* in_sizes, int n_in,
                              void* d_out, int out_size) {
    (void)in_sizes; (void)n_in; (void)out_size;
    const float* zi = (const float*)d_in[0];
    const float* zj = (const float*)d_in[1];
    float* out = (float*)d_out;

    size_t smem = 1024 + 3 * 32768;   // pad + A + 2x B = 97 KB -> 2 CTAs/SM
    cudaFuncSetAttribute(k_sim, cudaFuncAttributeMaxDynamicSharedMemorySize,
                         (int)smem);

    k_normalize<<<NN / 16, 256>>>(zi, zj);
    k_sim<<<GRID_SIM, 256, smem>>>();
    k_final<<<256, 256>>>(zi, zj, out);
}